// round 1
// baseline (speedup 1.0000x reference)
#include <cuda_runtime.h>
#include <cstdio>

// Problem dims
#define NB 16
#define CH 32      // C == CO == 32
#define VV 2048
#define VCC 256
#define SSZ 64
#define LL 12
#define NJ (NB*CH*LL)          // 6144, column dim in T-layout: j = (n*LL+l)*CH + c
#define NGROUP (NB*LL)         // 192 groups of 32 channels per row

#define FN1 0.8f
#define FN2 0.2f
#define FN3 0.2f
#define FN4 0.2f

// Scratch (static device memory — no allocation allowed)
__device__ float g_xT[VV*NJ];
__device__ float g_t1[VV*NJ];
__device__ float g_t2[VV*NJ];
__device__ float g_hf[VV*NJ];
__device__ float g_xc[VCC*NJ];
__device__ float g_c1[VCC*NJ];
__device__ float g_c2[VCC*NJ];
__device__ float g_hc[VCC*NJ];
__device__ float g_sx[SSZ*NJ];
__device__ float g_s1[SSZ*NJ];
__device__ float g_s2[SSZ*NJ];
__device__ float g_hs[SSZ*NJ];
__device__ float g_as[SSZ*SSZ];
__device__ float g_sup0[SSZ*SSZ];
__device__ float g_sup1[SSZ*SSZ];

// ---------------------------------------------------------------------------
// Transpose x[N,C,V,L] -> xT[v, (n*L+l)*C + c]
// ---------------------------------------------------------------------------
__global__ void xT_kernel(const float* __restrict__ x) {
    long t = (long)blockIdx.x * blockDim.x + threadIdx.x;
    if (t >= (long)VV * NJ) return;
    int q = (int)(t % NJ);
    int v = (int)(t / NJ);
    int c = q & 31;
    int g = q >> 5;          // n*12 + l
    int n = g / LL;
    int l = g - n * LL;
    g_xT[t] = x[(((long)(n*CH + c) * VV + v) * LL) + l];
}

// ---------------------------------------------------------------------------
// Generic SGEMM:  C[m, j] = sum_k Aop[m,k] * B[k, j],  B/C are [*, NJ] row-major
// TRANSA=true : A stored [K, M] row-major (a[k*lda+m])   -> nconv style
// TRANSA=false: A stored [M, K] row-major (a[m*lda+k])   -> back-projection
// EPI=0: C = acc       EPI=1: C += scale * relu(acc)
// Tile: 128x64x8, 256 threads, 8x4 microtile
// ---------------------------------------------------------------------------
template<bool TRANSA, int EPI>
__global__ __launch_bounds__(256)
void sgemm_kernel(const float* __restrict__ A, int lda,
                  const float* __restrict__ B,
                  float* __restrict__ C,
                  int M, int K, float scale)
{
    __shared__ float As[8][132];
    __shared__ float Bs[8][64];

    const int bm = blockIdx.y * 128;
    const int bn = blockIdx.x * 64;
    const int tid = threadIdx.x;
    const int tm = (tid >> 4) * 8;
    const int tn = (tid & 15) * 4;

    float acc[8][4];
#pragma unroll
    for (int i = 0; i < 8; i++)
#pragma unroll
        for (int j = 0; j < 4; j++) acc[i][j] = 0.f;

    for (int k0 = 0; k0 < K; k0 += 8) {
        // --- load A tile ---
        if (TRANSA) {
            int kk = tid >> 5;            // 0..7
            int mm = (tid & 31) * 4;      // 0..124
#pragma unroll
            for (int u = 0; u < 4; u++) {
                int m = bm + mm + u;
                As[kk][mm + u] = (m < M) ? A[(long)(k0 + kk) * lda + m] : 0.f;
            }
        } else {
            int mm = tid >> 1;            // 0..127
            int kk0 = (tid & 1) * 4;      // 0 or 4
            int m = bm + mm;
            if (m < M) {
                const float4 av = *(const float4*)(A + (long)m * lda + k0 + kk0);
                As[kk0 + 0][mm] = av.x;
                As[kk0 + 1][mm] = av.y;
                As[kk0 + 2][mm] = av.z;
                As[kk0 + 3][mm] = av.w;
            } else {
                As[kk0 + 0][mm] = 0.f; As[kk0 + 1][mm] = 0.f;
                As[kk0 + 2][mm] = 0.f; As[kk0 + 3][mm] = 0.f;
            }
        }
        // --- load B tile (8x64) ---
        {
            int idx2 = tid * 2;
            int kb = idx2 >> 6;
            int cb = idx2 & 63;
            const float2 bv = *(const float2*)(B + (long)(k0 + kb) * NJ + bn + cb);
            Bs[kb][cb]     = bv.x;
            Bs[kb][cb + 1] = bv.y;
        }
        __syncthreads();

#pragma unroll
        for (int kk = 0; kk < 8; kk++) {
            float a[8], bb[4];
#pragma unroll
            for (int i = 0; i < 8; i++) a[i] = As[kk][tm + i];
#pragma unroll
            for (int j = 0; j < 4; j++) bb[j] = Bs[kk][tn + j];
#pragma unroll
            for (int i = 0; i < 8; i++)
#pragma unroll
                for (int j = 0; j < 4; j++) acc[i][j] += a[i] * bb[j];
        }
        __syncthreads();
    }

#pragma unroll
    for (int i = 0; i < 8; i++) {
        int m = bm + tm + i;
        if (m < M) {
            float* cp = C + (long)m * NJ + bn + tn;
            if (EPI == 0) {
                float4 v = make_float4(acc[i][0], acc[i][1], acc[i][2], acc[i][3]);
                *(float4*)cp = v;
            } else {
                float4 o = *(const float4*)cp;
                o.x += scale * fmaxf(acc[i][0], 0.f);
                o.y += scale * fmaxf(acc[i][1], 0.f);
                o.z += scale * fmaxf(acc[i][2], 0.f);
                o.w += scale * fmaxf(acc[i][3], 0.f);
                *(float4*)cp = o;
            }
        }
    }
}

// ---------------------------------------------------------------------------
// Channel mix: out[row, g*32+co] = b[co] + sum_c W[co,c]*X + W[co,32+c]*Y + W[co,64+c]*Z
// grid: (12 chunks of 16 groups, R rows); block: 512 threads = 16 groups x 32 co
// ---------------------------------------------------------------------------
__global__ __launch_bounds__(512)
void mix_kernel(const float* __restrict__ X, const float* __restrict__ Y,
                const float* __restrict__ Z, const float* __restrict__ W,
                const float* __restrict__ bias, float* __restrict__ out)
{
    __shared__ float sWt[96 * 32];  // sWt[k*32+co] = W[co*96+k]
    __shared__ float sx[16 * 32], sy[16 * 32], sz[16 * 32];

    const int row = blockIdx.y;
    const int chunk = blockIdx.x;             // 0..11
    const int tid = threadIdx.x;

    for (int j = tid; j < 96 * 32; j += 512) {
        int co = j & 31, k = j >> 5;
        sWt[j] = W[co * 96 + k];
    }
    {
        long base = (long)row * NJ + chunk * 512;
        sx[tid] = X[base + tid];
        sy[tid] = Y[base + tid];
        sz[tid] = Z[base + tid];
    }
    __syncthreads();

    const int g = tid >> 5;
    const int co = tid & 31;
    float acc = bias[co];
#pragma unroll
    for (int c = 0; c < 32; c++) {
        acc += sWt[c * 32 + co]        * sx[g * 32 + c];
        acc += sWt[(32 + c) * 32 + co] * sy[g * 32 + c];
        acc += sWt[(64 + c) * 32 + co] * sz[g * 32 + c];
    }
    out[(long)row * NJ + chunk * 512 + tid] = acc;
}

// ---------------------------------------------------------------------------
// as_mat[s1,s2] = relu( sum_i sxg(p1(i))[s1] * sxg(p2(i))[s2] - 0.5 )
// i = (c*N + n)*L + l  for the s1 side ; i = (l*N + n)*C + c for the s2 side
// ---------------------------------------------------------------------------
__global__ void asmat_kernel() {
    const int s1 = blockIdx.x;
    __shared__ float a1[NJ];
    for (int i = threadIdx.x; i < NJ; i += blockDim.x) {
        int c = i / (NB * LL);
        int r = i - c * (NB * LL);
        int n = r / LL;
        int l = r - n * LL;
        a1[i] = g_sx[(long)s1 * NJ + (n * LL + l) * CH + c];
    }
    __syncthreads();
    const int s2 = threadIdx.x;
    if (s2 < SSZ) {
        const float* row2 = g_sx + (long)s2 * NJ;
        float acc = 0.f;
        int i = 0;
        for (int l = 0; l < LL; l++)
            for (int n = 0; n < NB; n++) {
                int base2 = (n * LL + l) * CH;
#pragma unroll
                for (int c = 0; c < CH; c++) acc += a1[i++] * row2[base2 + c];
            }
        g_as[s1 * SSZ + s2] = fmaxf(acc - 0.5f, 0.f);
    }
}

// ---------------------------------------------------------------------------
// sup0 = softmax(rownorm(as)); sup1 = softmax(rownorm(as^T)); one block per row
// ---------------------------------------------------------------------------
__global__ void supnorm_kernel() {
    __shared__ float sh[SSZ];
    const int s = blockIdx.x;
    const int t = threadIdx.x;
    float rv = g_as[s * SSZ + t];
    float cv = g_as[t * SSZ + s];

    // ---- row-normalized softmax -> sup0 ----
    sh[t] = rv; __syncthreads();
    for (int o = 32; o > 0; o >>= 1) { if (t < o) sh[t] += sh[t + o]; __syncthreads(); }
    float rs = sh[0]; __syncthreads();
    float xr = (rs > 0.f) ? rv / rs : 0.f;
    sh[t] = xr; __syncthreads();
    for (int o = 32; o > 0; o >>= 1) { if (t < o) sh[t] = fmaxf(sh[t], sh[t + o]); __syncthreads(); }
    float mx = sh[0]; __syncthreads();
    float e = expf(xr - mx);
    sh[t] = e; __syncthreads();
    for (int o = 32; o > 0; o >>= 1) { if (t < o) sh[t] += sh[t + o]; __syncthreads(); }
    g_sup0[s * SSZ + t] = e / sh[0];
    __syncthreads();

    // ---- column-normalized softmax -> sup1 ----
    sh[t] = cv; __syncthreads();
    for (int o = 32; o > 0; o >>= 1) { if (t < o) sh[t] += sh[t + o]; __syncthreads(); }
    float cs = sh[0]; __syncthreads();
    float xc2 = (cs > 0.f) ? cv / cs : 0.f;
    sh[t] = xc2; __syncthreads();
    for (int o = 32; o > 0; o >>= 1) { if (t < o) sh[t] = fmaxf(sh[t], sh[t + o]); __syncthreads(); }
    float mx2 = sh[0]; __syncthreads();
    float e2 = expf(xc2 - mx2);
    sh[t] = e2; __syncthreads();
    for (int o = 32; o > 0; o >>= 1) { if (t < o) sh[t] += sh[t + o]; __syncthreads(); }
    g_sup1[s * SSZ + t] = e2 / sh[0];
}

// ---------------------------------------------------------------------------
// Pack T-layout [R, NJ] back to reference layout [N, CO, R, L]
// ---------------------------------------------------------------------------
__global__ void pack_kernel(const float* __restrict__ src, int R, float* __restrict__ out) {
    long total = (long)NB * CH * R * LL;
    long idx = (long)blockIdx.x * blockDim.x + threadIdx.x;
    if (idx >= total) return;
    int l = (int)(idx % LL);
    long r1 = idx / LL;
    int v = (int)(r1 % R);
    long r2 = r1 / R;
    int co = (int)(r2 % CH);
    int n = (int)(r2 / CH);
    out[idx] = src[(long)v * NJ + (n * LL + l) * CH + co];
}

// ---------------------------------------------------------------------------
static inline void launch_gemm_T(const float* A, int lda, const float* B, float* C,
                                 int M, int K) {
    dim3 grid(NJ / 64, (M + 127) / 128);
    sgemm_kernel<true, 0><<<grid, 256>>>(A, lda, B, C, M, K, 0.f);
}
static inline void launch_gemm_T_res(const float* A, int lda, const float* B, float* C,
                                     int M, int K, float scale) {
    dim3 grid(NJ / 64, (M + 127) / 128);
    sgemm_kernel<true, 1><<<grid, 256>>>(A, lda, B, C, M, K, scale);
}
static inline void launch_gemm_N_res(const float* A, int lda, const float* B, float* C,
                                     int M, int K, float scale) {
    dim3 grid(NJ / 64, (M + 127) / 128);
    sgemm_kernel<false, 1><<<grid, 256>>>(A, lda, B, C, M, K, scale);
}

extern "C" void kernel_launch(void* const* d_in, const int* in_sizes, int n_in,
                              void* d_out, int out_size)
{
    const float* x         = (const float*)d_in[0];
    const float* support   = (const float*)d_in[1];   // [2, V, V]
    const float* support_c = (const float*)d_in[2];   // [2, VC, VC]
    const float* acs       = (const float*)d_in[3];   // [VC, S]
    const float* afc       = (const float*)d_in[4];   // [V, VC]
    const float* W         = (const float*)d_in[5];   // [CO, 3C]
    const float* bias      = (const float*)d_in[6];   // [CO]
    float* out = (float*)d_out;

    float *xT, *t1, *t2, *hf, *xc, *c1, *c2, *hc, *sx, *s1, *s2, *hs, *sup0, *sup1;
    cudaGetSymbolAddress((void**)&xT, g_xT);
    cudaGetSymbolAddress((void**)&t1, g_t1);
    cudaGetSymbolAddress((void**)&t2, g_t2);
    cudaGetSymbolAddress((void**)&hf, g_hf);
    cudaGetSymbolAddress((void**)&xc, g_xc);
    cudaGetSymbolAddress((void**)&c1, g_c1);
    cudaGetSymbolAddress((void**)&c2, g_c2);
    cudaGetSymbolAddress((void**)&hc, g_hc);
    cudaGetSymbolAddress((void**)&sx, g_sx);
    cudaGetSymbolAddress((void**)&s1, g_s1);
    cudaGetSymbolAddress((void**)&s2, g_s2);
    cudaGetSymbolAddress((void**)&hs, g_hs);
    cudaGetSymbolAddress((void**)&sup0, g_sup0);
    cudaGetSymbolAddress((void**)&sup1, g_sup1);

    // 1. x -> T layout
    {
        long total = (long)VV * NJ;
        xT_kernel<<<(unsigned)((total + 255) / 256), 256>>>(x);
    }

    // 2. fine nconv: t1 = A1^T.x, t2 = A2^T.x  (the 103 GFLOP)
    launch_gemm_T(support,            VV, xT, t1, VV, VV);
    launch_gemm_T(support + (long)VV*VV, VV, xT, t2, VV, VV);

    // 3. coarse projection xc = afc^T . x
    launch_gemm_T(afc, VCC, xT, xc, VCC, VV);

    // 4. hf = gcn fine
    { dim3 grid(12, VV); mix_kernel<<<grid, 512>>>(xT, t1, t2, W, bias, hf); }

    // 5. coarse nconv + gcn
    launch_gemm_T(support_c,             VCC, xc, c1, VCC, VCC);
    launch_gemm_T(support_c + VCC*VCC,   VCC, xc, c2, VCC, VCC);
    { dim3 grid(12, VCC); mix_kernel<<<grid, 512>>>(xc, c1, c2, W, bias, hc); }

    // 6. super projection sxg = acs^T . xc
    launch_gemm_T(acs, SSZ, xc, sx, SSZ, VCC);

    // 7. adaptive super supports
    asmat_kernel<<<SSZ, 256>>>();
    supnorm_kernel<<<SSZ, SSZ>>>();

    // 8. super nconv + gcn
    launch_gemm_T(sup0, SSZ, sx, s1, SSZ, SSZ);
    launch_gemm_T(sup1, SSZ, sx, s2, SSZ, SSZ);
    { dim3 grid(12, SSZ); mix_kernel<<<grid, 512>>>(sx, s1, s2, W, bias, hs); }

    // 9. hierarchical residual fusions
    launch_gemm_N_res(acs, SSZ, hs, hc, VCC, SSZ, FN1);   // hc += N1*relu(acs . hs)
    launch_gemm_N_res(afc, VCC, hc, hf, VV,  VCC, FN2);   // hf += N2*relu(afc . hc)
    launch_gemm_T_res(afc, VCC, hf, hc, VCC, VV,  FN3);   // hc += N3*relu(afc^T . hf)
    launch_gemm_T_res(acs, SSZ, hc, hs, SSZ, VCC, FN4);   // hs += N4*relu(acs^T . hc)

    // 10. pack outputs: [hf | hc | hs] in reference [N,CO,*,L] layouts
    const long off_hf = 0;
    const long off_hc = (long)NB * CH * VV * LL;                 // 12582912
    const long off_hs = off_hc + (long)NB * CH * VCC * LL;       // 14155776
    {
        long tot = (long)NB * CH * VV * LL;
        pack_kernel<<<(unsigned)((tot + 255) / 256), 256>>>(hf, VV, out + off_hf);
    }
    {
        long tot = (long)NB * CH * VCC * LL;
        pack_kernel<<<(unsigned)((tot + 255) / 256), 256>>>(hc, VCC, out + off_hc);
    }
    {
        long tot = (long)NB * CH * SSZ * LL;
        pack_kernel<<<(unsigned)((tot + 255) / 256), 256>>>(hs, SSZ, out + off_hs);
    }
}

// round 3
// speedup vs baseline: 1.0626x; 1.0626x over previous
#include <cuda_runtime.h>

// Problem dims
#define NB 16
#define CH 32      // C == CO == 32
#define VV 2048
#define VCC 256
#define SSZ 64
#define LL 12
#define NJ (NB*CH*LL)          // 6144

#define FN1 0.8f
#define FN2 0.2f
#define FN3 0.2f
#define FN4 0.2f

// Scratch (static device memory — no allocation allowed)
__device__ float g_xT[VV*NJ];
__device__ float g_t1[VV*NJ];
__device__ float g_t2[VV*NJ];
__device__ float g_hf[VV*NJ];
__device__ float g_xc[VCC*NJ];
__device__ float g_c1[VCC*NJ];
__device__ float g_c2[VCC*NJ];
__device__ float g_hc[VCC*NJ];
__device__ float g_sx[SSZ*NJ];
__device__ float g_s1[SSZ*NJ];
__device__ float g_s2[SSZ*NJ];
__device__ float g_hs[SSZ*NJ];
__device__ float g_as[SSZ*SSZ];
__device__ float g_sup0[SSZ*SSZ];
__device__ float g_sup1[SSZ*SSZ];

// ---------------------------------------------------------------------------
// f32x2 packed helpers (Blackwell): 2 FMAs per instruction on the fma pipe
// ---------------------------------------------------------------------------
__device__ __forceinline__ unsigned long long splat2(float b) {
    unsigned long long r;
    unsigned int u = __float_as_uint(b);
    asm("mov.b64 %0, {%1, %1};" : "=l"(r) : "r"(u));
    return r;
}
__device__ __forceinline__ void ffma2(unsigned long long& d,
                                      unsigned long long a,
                                      unsigned long long b) {
    asm("fma.rn.f32x2 %0, %1, %2, %0;" : "+l"(d) : "l"(a), "l"(b));
}
__device__ __forceinline__ float2 unpack2(unsigned long long a) {
    unsigned int lo, hi;
    asm("mov.b64 {%0, %1}, %2;" : "=r"(lo), "=r"(hi) : "l"(a));
    return make_float2(__uint_as_float(lo), __uint_as_float(hi));
}

// ---------------------------------------------------------------------------
// Transpose x[N,C,V,L] -> xT[v, (n*L+l)*C + c]
// ---------------------------------------------------------------------------
__global__ void xT_kernel(const float* __restrict__ x) {
    long t = (long)blockIdx.x * blockDim.x + threadIdx.x;
    if (t >= (long)VV * NJ) return;
    int q = (int)(t % NJ);
    int v = (int)(t / NJ);
    int c = q & 31;
    int g = q >> 5;          // n*12 + l
    int n = g / LL;
    int l = g - n * LL;
    g_xT[t] = x[(((long)(n*CH + c) * VV + v) * LL) + l];
}

// ---------------------------------------------------------------------------
// Packed-f32x2 SGEMM: C[m, j] = sum_k Aop[m,k] * B[k, j]; B,C row-major [*, NJ]
// TRANSA=true : A stored [K, M] row-major (a[k*lda+m])
// TRANSA=false: A stored [M, K] row-major (a[m*lda+k])
// EPI=0: C = acc ;  EPI=1: C += scale * relu(acc)
// Tile: BM x 128 x 16 (BM = MT*16), 256 threads, microtile MT x 8 per thread
// Accumulators packed in f32x2 pairs along m. Double-buffered smem.
// ---------------------------------------------------------------------------
template<int MT, bool TRANSA, int EPI>
__global__ __launch_bounds__(256, 2)
void gemm2_kernel(const float* __restrict__ A, int lda,
                  const float* __restrict__ B,
                  float* __restrict__ C,
                  int M, int K, float scale)
{
    constexpr int BM = MT * 16;
    constexpr int KT = 16;
    constexpr int NP = MT / 2;
    __shared__ __align__(16) float As[2][KT * BM];
    __shared__ __align__(16) float Bs[2][KT * 128];

    const int bm = blockIdx.y * BM;
    const int bn = blockIdx.x * 128;
    const int tid = threadIdx.x;
    const int tm = (tid >> 4) * MT;
    const int tn = (tid & 15) * 8;

    unsigned long long acc[NP][8];
#pragma unroll
    for (int ip = 0; ip < NP; ip++)
#pragma unroll
        for (int j = 0; j < 8; j++) acc[ip][j] = 0ull;

    // --- global-load index precompute ---
    const int a_kk = tid >> 4;              // TRANSA row within k-tile
    const int a_m4 = (tid & 15) * MT;       // TRANSA m offset (MT floats/thread)
    const int an_row = (MT == 8) ? (tid >> 1) : (tid >> 2);       // !TRANSA
    const int an_kk0 = (MT == 8) ? ((tid & 1) * 8) : ((tid & 3) * 4);
    const int b_kb = tid >> 4;
    const int b_nb = (tid & 15) * 8;

    float4 ra0, ra1, rb0, rb1;

    auto ldgA = [&](int k0) {
        if (TRANSA) {
            const float* p = A + (size_t)(k0 + a_kk) * lda + bm + a_m4;
            ra0 = *(const float4*)p;
            if (MT == 8) ra1 = *(const float4*)(p + 4);
        } else {
            const float* p = A + (size_t)(bm + an_row) * lda + k0 + an_kk0;
            ra0 = *(const float4*)p;
            if (MT == 8) ra1 = *(const float4*)(p + 4);
        }
    };
    auto stsA = [&](int pb) {
        if (TRANSA) {
            float4* d = (float4*)&As[pb][a_kk * BM + a_m4];
            d[0] = ra0;
            if (MT == 8) d[1] = ra1;
        } else {
            As[pb][(an_kk0 + 0) * BM + an_row] = ra0.x;
            As[pb][(an_kk0 + 1) * BM + an_row] = ra0.y;
            As[pb][(an_kk0 + 2) * BM + an_row] = ra0.z;
            As[pb][(an_kk0 + 3) * BM + an_row] = ra0.w;
            if (MT == 8) {
                As[pb][(an_kk0 + 4) * BM + an_row] = ra1.x;
                As[pb][(an_kk0 + 5) * BM + an_row] = ra1.y;
                As[pb][(an_kk0 + 6) * BM + an_row] = ra1.z;
                As[pb][(an_kk0 + 7) * BM + an_row] = ra1.w;
            }
        }
    };
    auto ldgB = [&](int k0) {
        const float* p = B + (size_t)(k0 + b_kb) * NJ + bn + b_nb;
        rb0 = *(const float4*)p;
        rb1 = *(const float4*)(p + 4);
    };
    auto stsB = [&](int pb) {
        float4* d = (float4*)&Bs[pb][b_kb * 128 + b_nb];
        d[0] = rb0;
        d[1] = rb1;
    };

    const int nk = K / KT;
    ldgA(0); ldgB(0);
    stsA(0); stsB(0);
    int p = 0;

    for (int kt = 0; kt < nk; kt++) {
        __syncthreads();
        const bool more = (kt + 1 < nk);
        if (more) { ldgA((kt + 1) * KT); ldgB((kt + 1) * KT); }

#pragma unroll
        for (int kk = 0; kk < KT; kk++) {
            unsigned long long a2[NP];
            const float* as = &As[p][kk * BM + tm];
            {
                ulonglong2 t0 = *(const ulonglong2*)as;
                a2[0] = t0.x; a2[1] = t0.y;
                if (MT == 8) {
                    ulonglong2 t1 = *(const ulonglong2*)(as + 4);
                    a2[2] = t1.x; a2[3] = t1.y;
                }
            }
            const float* bsp = &Bs[p][kk * 128 + tn];
            float4 b0 = *(const float4*)bsp;
            float4 b1 = *(const float4*)(bsp + 4);
            unsigned long long b2[8];
            b2[0] = splat2(b0.x); b2[1] = splat2(b0.y);
            b2[2] = splat2(b0.z); b2[3] = splat2(b0.w);
            b2[4] = splat2(b1.x); b2[5] = splat2(b1.y);
            b2[6] = splat2(b1.z); b2[7] = splat2(b1.w);
#pragma unroll
            for (int ip = 0; ip < NP; ip++)
#pragma unroll
                for (int j = 0; j < 8; j++)
                    ffma2(acc[ip][j], a2[ip], b2[j]);
        }

        if (more) { stsA(p ^ 1); stsB(p ^ 1); }
        p ^= 1;
    }

    // ---- epilogue: unpack f32x2 (pair covers rows m, m+1) ----
#pragma unroll
    for (int ip = 0; ip < NP; ip++) {
        const int r0 = bm + tm + 2 * ip;
        float lo[8], hi[8];
#pragma unroll
        for (int j = 0; j < 8; j++) {
            float2 v = unpack2(acc[ip][j]);
            lo[j] = v.x; hi[j] = v.y;
        }
        float* c0 = C + (size_t)r0 * NJ + bn + tn;
        float* c1 = c0 + NJ;
        if (EPI == 0) {
            *(float4*)c0       = make_float4(lo[0], lo[1], lo[2], lo[3]);
            *(float4*)(c0 + 4) = make_float4(lo[4], lo[5], lo[6], lo[7]);
            *(float4*)c1       = make_float4(hi[0], hi[1], hi[2], hi[3]);
            *(float4*)(c1 + 4) = make_float4(hi[4], hi[5], hi[6], hi[7]);
        } else {
            float4 o0 = *(const float4*)c0, o1 = *(const float4*)(c0 + 4);
            float4 o2 = *(const float4*)c1, o3 = *(const float4*)(c1 + 4);
            o0.x += scale * fmaxf(lo[0], 0.f); o0.y += scale * fmaxf(lo[1], 0.f);
            o0.z += scale * fmaxf(lo[2], 0.f); o0.w += scale * fmaxf(lo[3], 0.f);
            o1.x += scale * fmaxf(lo[4], 0.f); o1.y += scale * fmaxf(lo[5], 0.f);
            o1.z += scale * fmaxf(lo[6], 0.f); o1.w += scale * fmaxf(lo[7], 0.f);
            o2.x += scale * fmaxf(hi[0], 0.f); o2.y += scale * fmaxf(hi[1], 0.f);
            o2.z += scale * fmaxf(hi[2], 0.f); o2.w += scale * fmaxf(hi[3], 0.f);
            o3.x += scale * fmaxf(hi[4], 0.f); o3.y += scale * fmaxf(hi[5], 0.f);
            o3.z += scale * fmaxf(hi[6], 0.f); o3.w += scale * fmaxf(hi[7], 0.f);
            *(float4*)c0 = o0; *(float4*)(c0 + 4) = o1;
            *(float4*)c1 = o2; *(float4*)(c1 + 4) = o3;
        }
    }
}

// ---------------------------------------------------------------------------
// Channel mix: out[row, g*32+co] = b[co] + sum_c W[co,c]*X + W[co,32+c]*Y + W[co,64+c]*Z
// ---------------------------------------------------------------------------
__global__ __launch_bounds__(512)
void mix_kernel(const float* __restrict__ X, const float* __restrict__ Y,
                const float* __restrict__ Z, const float* __restrict__ W,
                const float* __restrict__ bias, float* __restrict__ out)
{
    __shared__ float sWt[96 * 32];  // sWt[k*32+co] = W[co*96+k]
    __shared__ float sx[16 * 32], sy[16 * 32], sz[16 * 32];

    const int row = blockIdx.y;
    const int chunk = blockIdx.x;             // 0..11
    const int tid = threadIdx.x;

    for (int j = tid; j < 96 * 32; j += 512) {
        int co = j & 31, k = j >> 5;
        sWt[j] = W[co * 96 + k];
    }
    {
        long base = (long)row * NJ + chunk * 512;
        sx[tid] = X[base + tid];
        sy[tid] = Y[base + tid];
        sz[tid] = Z[base + tid];
    }
    __syncthreads();

    const int g = tid >> 5;
    const int co = tid & 31;
    float acc = bias[co];
#pragma unroll
    for (int c = 0; c < 32; c++) {
        acc += sWt[c * 32 + co]        * sx[g * 32 + c];
        acc += sWt[(32 + c) * 32 + co] * sy[g * 32 + c];
        acc += sWt[(64 + c) * 32 + co] * sz[g * 32 + c];
    }
    out[(long)row * NJ + chunk * 512 + tid] = acc;
}

// ---------------------------------------------------------------------------
// as_mat[s1,s2] = relu( sum_i sxg(p1(i))[s1] * sxg(p2(i))[s2] - 0.5 )
// ---------------------------------------------------------------------------
__global__ void asmat_kernel() {
    const int s1 = blockIdx.x;
    __shared__ float a1[NJ];
    for (int i = threadIdx.x; i < NJ; i += blockDim.x) {
        int c = i / (NB * LL);
        int r = i - c * (NB * LL);
        int n = r / LL;
        int l = r - n * LL;
        a1[i] = g_sx[(long)s1 * NJ + (n * LL + l) * CH + c];
    }
    __syncthreads();
    const int s2 = threadIdx.x;
    if (s2 < SSZ) {
        const float* row2 = g_sx + (long)s2 * NJ;
        float acc = 0.f;
        int i = 0;
        for (int l = 0; l < LL; l++)
            for (int n = 0; n < NB; n++) {
                int base2 = (n * LL + l) * CH;
#pragma unroll
                for (int c = 0; c < CH; c++) acc += a1[i++] * row2[base2 + c];
            }
        g_as[s1 * SSZ + s2] = fmaxf(acc - 0.5f, 0.f);
    }
}

// ---------------------------------------------------------------------------
// sup0 = softmax(rownorm(as)); sup1 = softmax(rownorm(as^T)); one block per row
// ---------------------------------------------------------------------------
__global__ void supnorm_kernel() {
    __shared__ float sh[SSZ];
    const int s = blockIdx.x;
    const int t = threadIdx.x;
    float rv = g_as[s * SSZ + t];
    float cv = g_as[t * SSZ + s];

    sh[t] = rv; __syncthreads();
    for (int o = 32; o > 0; o >>= 1) { if (t < o) sh[t] += sh[t + o]; __syncthreads(); }
    float rs = sh[0]; __syncthreads();
    float xr = (rs > 0.f) ? rv / rs : 0.f;
    sh[t] = xr; __syncthreads();
    for (int o = 32; o > 0; o >>= 1) { if (t < o) sh[t] = fmaxf(sh[t], sh[t + o]); __syncthreads(); }
    float mx = sh[0]; __syncthreads();
    float e = expf(xr - mx);
    sh[t] = e; __syncthreads();
    for (int o = 32; o > 0; o >>= 1) { if (t < o) sh[t] += sh[t + o]; __syncthreads(); }
    g_sup0[s * SSZ + t] = e / sh[0];
    __syncthreads();

    sh[t] = cv; __syncthreads();
    for (int o = 32; o > 0; o >>= 1) { if (t < o) sh[t] += sh[t + o]; __syncthreads(); }
    float cs = sh[0]; __syncthreads();
    float xc2 = (cs > 0.f) ? cv / cs : 0.f;
    sh[t] = xc2; __syncthreads();
    for (int o = 32; o > 0; o >>= 1) { if (t < o) sh[t] = fmaxf(sh[t], sh[t + o]); __syncthreads(); }
    float mx2 = sh[0]; __syncthreads();
    float e2 = expf(xc2 - mx2);
    sh[t] = e2; __syncthreads();
    for (int o = 32; o > 0; o >>= 1) { if (t < o) sh[t] += sh[t + o]; __syncthreads(); }
    g_sup1[s * SSZ + t] = e2 / sh[0];
}

// ---------------------------------------------------------------------------
// Pack T-layout [R, NJ] back to reference layout [N, CO, R, L]
// ---------------------------------------------------------------------------
__global__ void pack_kernel(const float* __restrict__ src, int R, float* __restrict__ out) {
    long total = (long)NB * CH * R * LL;
    long idx = (long)blockIdx.x * blockDim.x + threadIdx.x;
    if (idx >= total) return;
    int l = (int)(idx % LL);
    long r1 = idx / LL;
    int v = (int)(r1 % R);
    long r2 = r1 / R;
    int co = (int)(r2 % CH);
    int n = (int)(r2 / CH);
    out[idx] = src[(long)v * NJ + (n * LL + l) * CH + co];
}

// ---------------------------------------------------------------------------
extern "C" void kernel_launch(void* const* d_in, const int* in_sizes, int n_in,
                              void* d_out, int out_size)
{
    const float* x         = (const float*)d_in[0];
    const float* support   = (const float*)d_in[1];   // [2, V, V]
    const float* support_c = (const float*)d_in[2];   // [2, VC, VC]
    const float* acs       = (const float*)d_in[3];   // [VC, S]
    const float* afc       = (const float*)d_in[4];   // [V, VC]
    const float* W         = (const float*)d_in[5];   // [CO, 3C]
    const float* bias      = (const float*)d_in[6];   // [CO]
    float* out = (float*)d_out;

    float *xT, *t1, *t2, *hf, *xc, *c1, *c2, *hc, *sx, *s1, *s2, *hs, *sup0, *sup1;
    cudaGetSymbolAddress((void**)&xT, g_xT);
    cudaGetSymbolAddress((void**)&t1, g_t1);
    cudaGetSymbolAddress((void**)&t2, g_t2);
    cudaGetSymbolAddress((void**)&hf, g_hf);
    cudaGetSymbolAddress((void**)&xc, g_xc);
    cudaGetSymbolAddress((void**)&c1, g_c1);
    cudaGetSymbolAddress((void**)&c2, g_c2);
    cudaGetSymbolAddress((void**)&hc, g_hc);
    cudaGetSymbolAddress((void**)&sx, g_sx);
    cudaGetSymbolAddress((void**)&s1, g_s1);
    cudaGetSymbolAddress((void**)&s2, g_s2);
    cudaGetSymbolAddress((void**)&hs, g_hs);
    cudaGetSymbolAddress((void**)&sup0, g_sup0);
    cudaGetSymbolAddress((void**)&sup1, g_sup1);

    // 1. x -> T layout
    {
        long total = (long)VV * NJ;
        xT_kernel<<<(unsigned)((total + 255) / 256), 256>>>(x);
    }

    // 2. fine nconv: t1 = A1^T.x, t2 = A2^T.x  (the 103 GFLOP)
    {
        dim3 grid(NJ / 128, VV / 128);
        gemm2_kernel<8, true, 0><<<grid, 256>>>(support,              VV, xT, t1, VV, VV, 0.f);
        gemm2_kernel<8, true, 0><<<grid, 256>>>(support + (long)VV*VV, VV, xT, t2, VV, VV, 0.f);
    }

    // 3. coarse projection xc = afc^T . x   (M=256 -> BM=64 tiles)
    {
        dim3 grid(NJ / 128, VCC / 64);
        gemm2_kernel<4, true, 0><<<grid, 256>>>(afc, VCC, xT, xc, VCC, VV, 0.f);
    }

    // 4. hf = gcn fine
    { dim3 grid(12, VV); mix_kernel<<<grid, 512>>>(xT, t1, t2, W, bias, hf); }

    // 5. coarse nconv + gcn
    {
        dim3 grid(NJ / 128, VCC / 64);
        gemm2_kernel<4, true, 0><<<grid, 256>>>(support_c,           VCC, xc, c1, VCC, VCC, 0.f);
        gemm2_kernel<4, true, 0><<<grid, 256>>>(support_c + VCC*VCC, VCC, xc, c2, VCC, VCC, 0.f);
    }
    { dim3 grid(12, VCC); mix_kernel<<<grid, 512>>>(xc, c1, c2, W, bias, hc); }

    // 6. super projection sxg = acs^T . xc   (M=64)
    {
        dim3 grid(NJ / 128, SSZ / 64);
        gemm2_kernel<4, true, 0><<<grid, 256>>>(acs, SSZ, xc, sx, SSZ, VCC, 0.f);
    }

    // 7. adaptive super supports
    asmat_kernel<<<SSZ, 256>>>();
    supnorm_kernel<<<SSZ, SSZ>>>();

    // 8. super nconv + gcn
    {
        dim3 grid(NJ / 128, SSZ / 64);
        gemm2_kernel<4, true, 0><<<grid, 256>>>(sup0, SSZ, sx, s1, SSZ, SSZ, 0.f);
        gemm2_kernel<4, true, 0><<<grid, 256>>>(sup1, SSZ, sx, s2, SSZ, SSZ, 0.f);
    }
    { dim3 grid(12, SSZ); mix_kernel<<<grid, 512>>>(sx, s1, s2, W, bias, hs); }

    // 9. hierarchical residual fusions
    {
        dim3 g1(NJ / 128, VCC / 64);   // hc += N1*relu(acs . hs)      [M=256,K=64]
        gemm2_kernel<4, false, 1><<<g1, 256>>>(acs, SSZ, hs, hc, VCC, SSZ, FN1);
        dim3 g2(NJ / 128, VV / 128);   // hf += N2*relu(afc . hc)      [M=2048,K=256]
        gemm2_kernel<8, false, 1><<<g2, 256>>>(afc, VCC, hc, hf, VV, VCC, FN2);
        dim3 g3(NJ / 128, VCC / 64);   // hc += N3*relu(afc^T . hf)    [M=256,K=2048]
        gemm2_kernel<4, true, 1><<<g3, 256>>>(afc, VCC, hf, hc, VCC, VV, FN3);
        dim3 g4(NJ / 128, SSZ / 64);   // hs += N4*relu(acs^T . hc)    [M=64,K=2048]
        gemm2_kernel<4, true, 1><<<g4, 256>>>(acs, SSZ, hc, hs, SSZ, VCC, FN4);
    }

    // 10. pack outputs: [hf | hc | hs] in reference [N,CO,*,L] layouts
    const long off_hc = (long)NB * CH * VV * LL;
    const long off_hs = off_hc + (long)NB * CH * VCC * LL;
    {
        long tot = (long)NB * CH * VV * LL;
        pack_kernel<<<(unsigned)((tot + 255) / 256), 256>>>(hf, VV, out);
    }
    {
        long tot = (long)NB * CH * VCC * LL;
        pack_kernel<<<(unsigned)((tot + 255) / 256), 256>>>(hc, VCC, out + off_hc);
    }
    {
        long tot = (long)NB * CH * SSZ * LL;
        pack_kernel<<<(unsigned)((tot + 255) / 256), 256>>>(hs, SSZ, out + off_hs);
    }
}

// round 5
// speedup vs baseline: 2.3868x; 2.2462x over previous
#include <cuda_runtime.h>
#include <cuda_bf16.h>
#include <cstdint>

// ---------------- problem dims ----------------
#define NB 16
#define CH 32
#define VV 2048
#define VCC 256
#define SSZ 64
#define LL 12
#define JD (NB*CH*LL)     // 6144 rows, j = (n*LL+l)*CH + c

#define FN1 0.8f
#define FN2 0.2f
#define FN3 0.2f
#define FN4 0.2f

typedef __nv_bfloat16 bf16;

// ---------------- fp32 scratch pool ----------------
#define SZ_BIG   ((size_t)JD*VV)
#define SZ_MED   ((size_t)JD*VCC)
#define SZ_SML   ((size_t)JD*SSZ)
constexpr size_t F_XJ = 0;
constexpr size_t F_T1 = F_XJ + SZ_BIG;
constexpr size_t F_T2 = F_T1 + SZ_BIG;
constexpr size_t F_HF = F_T2 + SZ_BIG;
constexpr size_t F_XC = F_HF + SZ_BIG;
constexpr size_t F_C1 = F_XC + SZ_MED;
constexpr size_t F_C2 = F_C1 + SZ_MED;
constexpr size_t F_HC = F_C2 + SZ_MED;
constexpr size_t F_SX = F_HC + SZ_MED;
constexpr size_t F_S1 = F_SX + SZ_SML;
constexpr size_t F_S2 = F_S1 + SZ_SML;
constexpr size_t F_HS = F_S2 + SZ_SML;
constexpr size_t F_TOT = F_HS + SZ_SML;
__device__ __align__(256) float g_f[F_TOT];

// ---------------- bf16 scratch pool (hi/lo pairs) ----------------
constexpr size_t B_XJH = 0;
constexpr size_t B_XJL = B_XJH + SZ_BIG;
constexpr size_t B_HFH = B_XJL + SZ_BIG;
constexpr size_t B_HFL = B_HFH + SZ_BIG;
constexpr size_t B_XCH = B_HFL + SZ_BIG;
constexpr size_t B_XCL = B_XCH + SZ_MED;
constexpr size_t B_HCH = B_XCL + SZ_MED;
constexpr size_t B_HCL = B_HCH + SZ_MED;
constexpr size_t B_SXH = B_HCL + SZ_MED;
constexpr size_t B_SXL = B_SXH + SZ_SML;
constexpr size_t B_HSH = B_SXL + SZ_SML;
constexpr size_t B_HSL = B_HSH + SZ_SML;
constexpr size_t B_ST1H = B_HSL + SZ_SML;                 // supT1 [V,V]
constexpr size_t B_ST1L = B_ST1H + (size_t)VV*VV;
constexpr size_t B_ST2H = B_ST1L + (size_t)VV*VV;
constexpr size_t B_ST2L = B_ST2H + (size_t)VV*VV;
constexpr size_t B_AFTH = B_ST2L + (size_t)VV*VV;         // afcT [VC,V]
constexpr size_t B_AFTL = B_AFTH + (size_t)VCC*VV;
constexpr size_t B_AFNH = B_AFTL + (size_t)VCC*VV;        // afc  [V,VC]
constexpr size_t B_AFNL = B_AFNH + (size_t)VV*VCC;
constexpr size_t B_SC1H = B_AFNL + (size_t)VV*VCC;        // supcT1 [VC,VC]
constexpr size_t B_SC1L = B_SC1H + (size_t)VCC*VCC;
constexpr size_t B_SC2H = B_SC1L + (size_t)VCC*VCC;
constexpr size_t B_SC2L = B_SC2H + (size_t)VCC*VCC;
constexpr size_t B_ACTH = B_SC2L + (size_t)VCC*VCC;       // acsT [S,VC]
constexpr size_t B_ACTL = B_ACTH + (size_t)SSZ*VCC;
constexpr size_t B_ACNH = B_ACTL + (size_t)SSZ*VCC;       // acs  [VC,S]
constexpr size_t B_ACNL = B_ACNH + (size_t)VCC*SSZ;
constexpr size_t B_SP0H = B_ACNL + (size_t)VCC*SSZ;       // sup0T [S,S]
constexpr size_t B_SP0L = B_SP0H + (size_t)SSZ*SSZ;
constexpr size_t B_SP1H = B_SP0L + (size_t)SSZ*SSZ;
constexpr size_t B_SP1L = B_SP1H + (size_t)SSZ*SSZ;
constexpr size_t B_TOT  = B_SP1L + (size_t)SSZ*SSZ;
__device__ __align__(256) bf16 g_b[B_TOT];

__device__ float g_as[SSZ*SSZ];
__device__ float g_sup0[SSZ*SSZ];
__device__ float g_sup1[SSZ*SSZ];

// =======================================================================
// warp-mma helpers (sm_80+ baseline ISA — compiles for plain sm_103)
// =======================================================================
__device__ __forceinline__ uint32_t smem_u32(const void* p) {
    uint32_t a;
    asm("{ .reg .u64 t; cvta.to.shared.u64 t, %1; cvt.u32.u64 %0, t; }" : "=r"(a) : "l"(p));
    return a;
}
#define LDSM4(r, a) asm volatile( \
    "ldmatrix.sync.aligned.m8n8.x4.shared.b16 {%0,%1,%2,%3}, [%4];" \
    : "=r"((r)[0]), "=r"((r)[1]), "=r"((r)[2]), "=r"((r)[3]) : "r"(a))
#define LDSM2(r, a) asm volatile( \
    "ldmatrix.sync.aligned.m8n8.x2.shared.b16 {%0,%1}, [%2];" \
    : "=r"((r)[0]), "=r"((r)[1]) : "r"(a))
#define MMA16816(c, a, b) asm volatile( \
    "mma.sync.aligned.m16n8k16.row.col.f32.bf16.bf16.f32 " \
    "{%0,%1,%2,%3}, {%4,%5,%6,%7}, {%8,%9}, {%0,%1,%2,%3};" \
    : "+f"((c)[0]), "+f"((c)[1]), "+f"((c)[2]), "+f"((c)[3]) \
    : "r"((a)[0]), "r"((a)[1]), "r"((a)[2]), "r"((a)[3]), "r"((b)[0]), "r"((b)[1]))
__device__ __forceinline__ void cp16(uint32_t daddr, const void* gptr) {
    asm volatile("cp.async.cg.shared.global [%0], [%1], 16;" :: "r"(daddr), "l"(gptr));
}
#define CP_COMMIT() asm volatile("cp.async.commit_group;" ::: "memory")
#define CP_WAIT(n)  asm volatile("cp.async.wait_group %0;" :: "n"(n) : "memory")

// swizzled offset within a tile: row r (64B rows), 16B chunk c (0..3)
__device__ __forceinline__ uint32_t swz(int r, int c) {
    return (uint32_t)(r * 64 + ((c ^ (r & 3)) << 4));
}

// =======================================================================
// Tensor-core GEMM:  C[bm+j, bn+n] (+)= scale*relu( sum_k A[j,k]*B[n,k] )
// A: [JD, K] bf16 hi/lo K-major;  B: [N, K] bf16 hi/lo K-major
// block 128 x BN x 32, 256 threads (8 warps), double-buffered cp.async
// 3 split terms: AhBh + AhBl + AlBh (fp32-grade precision in fp32 acc)
// =======================================================================
template<int BN, int EPI>
__global__ __launch_bounds__(256, 1)
void gemm_mma(const bf16* __restrict__ Ah, const bf16* __restrict__ Al,
              const bf16* __restrict__ Bh, const bf16* __restrict__ Bl,
              float* __restrict__ C, int K, int ldc, float scale)
{
    extern __shared__ char smem[];
    constexpr int BM = 128, BK = 32;
    constexpr int WN = (BN == 128) ? 4 : 2;
    constexpr int WROWS = BM / (8 / WN);     // 64 (BN=128) / 32 (BN=64)
    constexpr int WCOLS = BN / WN;           // 32
    constexpr int FM = WROWS / 16;           // 4 / 2
    constexpr int FN = WCOLS / 8;            // 4
    constexpr int SA = BM * BK * 2;          // 8192
    constexpr int SB = BN * BK * 2;
    constexpr int STAGE = 2 * SA + 2 * SB;

    const int tid = threadIdx.x;
    const int warp = tid >> 5;
    const int lane = tid & 31;
    const int bm = blockIdx.y * BM;
    const int bn = blockIdx.x * BN;
    const int wm0 = (warp / WN) * WROWS;
    const int wn0 = (warp % WN) * WCOLS;
    const uint32_t sbase = smem_u32(smem);

    // ldmatrix lane offsets (constant across stages)
    uint32_t aoff[FM][2], boff[FN][2];
    {
        const int mat = lane >> 3, r8 = lane & 7;
#pragma unroll
        for (int fm = 0; fm < FM; fm++)
#pragma unroll
            for (int ks = 0; ks < 2; ks++) {
                int row = wm0 + fm * 16 + (mat & 1) * 8 + r8;
                aoff[fm][ks] = swz(row, ks * 2 + (mat >> 1));
            }
        const int rb = lane & 7, cs = (lane >> 3) & 1;
#pragma unroll
        for (int fn = 0; fn < FN; fn++)
#pragma unroll
            for (int ks = 0; ks < 2; ks++) {
                int row = wn0 + fn * 8 + rb;
                boff[fn][ks] = swz(row, ks * 2 + cs);
            }
    }

    float acc[FM][FN][4];
#pragma unroll
    for (int i = 0; i < FM; i++)
#pragma unroll
        for (int j = 0; j < FN; j++)
#pragma unroll
            for (int q = 0; q < 4; q++) acc[i][j][q] = 0.f;

    auto load_stage = [&](int k0, int buf) {
        const uint32_t st = sbase + buf * STAGE;
#pragma unroll
        for (int i = tid; i < 512; i += 256) {
            int r = i >> 2, c = i & 3;
            uint32_t o = swz(r, c);
            size_t g = (size_t)(bm + r) * K + k0 + c * 8;
            cp16(st + o,      Ah + g);
            cp16(st + SA + o, Al + g);
        }
        for (int i = tid; i < BN * 4; i += 256) {
            int r = i >> 2, c = i & 3;
            uint32_t o = swz(r, c);
            size_t g = (size_t)(bn + r) * K + k0 + c * 8;
            cp16(st + 2 * SA + o,      Bh + g);
            cp16(st + 2 * SA + SB + o, Bl + g);
        }
        CP_COMMIT();
    };

    const int nk = K / BK;
    load_stage(0, 0);
    int buf = 0;
    for (int kt = 0; kt < nk; kt++) {
        if (kt + 1 < nk) { load_stage((kt + 1) * BK, buf ^ 1); CP_WAIT(1); }
        else             { CP_WAIT(0); }
        __syncthreads();
        const uint32_t ab = sbase + buf * STAGE;
        const uint32_t bb = ab + 2 * SA;
#pragma unroll
        for (int ks = 0; ks < 2; ks++) {
            uint32_t ah[FM][4], al[FM][4], bh[FN][2], bl[FN][2];
#pragma unroll
            for (int fm = 0; fm < FM; fm++) {
                LDSM4(ah[fm], ab + aoff[fm][ks]);
                LDSM4(al[fm], ab + SA + aoff[fm][ks]);
            }
#pragma unroll
            for (int fn = 0; fn < FN; fn++) {
                LDSM2(bh[fn], bb + boff[fn][ks]);
                LDSM2(bl[fn], bb + SB + boff[fn][ks]);
            }
#pragma unroll
            for (int fm = 0; fm < FM; fm++)
#pragma unroll
                for (int fn = 0; fn < FN; fn++) {
                    MMA16816(acc[fm][fn], ah[fm], bh[fn]);
                    MMA16816(acc[fm][fn], ah[fm], bl[fn]);
                    MMA16816(acc[fm][fn], al[fm], bh[fn]);
                }
        }
        __syncthreads();
        buf ^= 1;
    }

    // epilogue
    const int er = bm + wm0 + (lane >> 2);
    const int ec = bn + wn0 + (lane & 3) * 2;
#pragma unroll
    for (int fm = 0; fm < FM; fm++)
#pragma unroll
        for (int fn = 0; fn < FN; fn++) {
            float* a = acc[fm][fn];
            float* p0 = C + (size_t)(er + fm * 16) * ldc + ec + fn * 8;
            float* p1 = p0 + 8 * (size_t)ldc;
            if (EPI == 0) {
                p0[0] = a[0]; p0[1] = a[1];
                p1[0] = a[2]; p1[1] = a[3];
            } else {
                p0[0] += scale * fmaxf(a[0], 0.f);
                p0[1] += scale * fmaxf(a[1], 0.f);
                p1[0] += scale * fmaxf(a[2], 0.f);
                p1[1] += scale * fmaxf(a[3], 0.f);
            }
        }
}

// =======================================================================
// build xj: x[N,C,V,L] -> xj[j, v] fp32 + bf16 hi/lo
// =======================================================================
__global__ void build_xj_kernel(const float* __restrict__ x) {
    size_t t = (size_t)blockIdx.x * blockDim.x + threadIdx.x;
    if (t >= SZ_BIG) return;
    int v = (int)(t % VV);
    int j = (int)(t / VV);
    int c = j & 31;
    int g = j >> 5;
    int n = g / LL;
    int l = g - n * LL;
    float val = x[((size_t)(n * CH + c) * VV + v) * LL + l];
    g_f[F_XJ + t] = val;
    bf16 h = __float2bfloat16(val);
    g_b[B_XJH + t] = h;
    g_b[B_XJL + t] = __float2bfloat16(val - __bfloat162float(h));
}

__global__ void split_kernel(const float* __restrict__ s, bf16* __restrict__ h,
                             bf16* __restrict__ l, size_t n) {
    size_t t = (size_t)blockIdx.x * blockDim.x + threadIdx.x;
    if (t >= n) return;
    float v = s[t];
    bf16 hh = __float2bfloat16(v);
    h[t] = hh;
    l[t] = __float2bfloat16(v - __bfloat162float(hh));
}

// transpose+split: src [K, M] fp32 -> dst [M, K] bf16 hi/lo
__global__ void tsplit_kernel(const float* __restrict__ s, bf16* __restrict__ h,
                              bf16* __restrict__ l, int K, int M) {
    __shared__ float t[32][33];
    const int kb = blockIdx.x * 32, mb = blockIdx.y * 32;
    const int tx = threadIdx.x, ty = threadIdx.y;
#pragma unroll
    for (int dy = 0; dy < 32; dy += 8)
        t[ty + dy][tx] = s[(size_t)(kb + ty + dy) * M + mb + tx];
    __syncthreads();
#pragma unroll
    for (int dy = 0; dy < 32; dy += 8) {
        float v = t[tx][ty + dy];
        size_t o = (size_t)(mb + ty + dy) * K + kb + tx;
        bf16 hh = __float2bfloat16(v);
        h[o] = hh;
        l[o] = __float2bfloat16(v - __bfloat162float(hh));
    }
}

// =======================================================================
// mix (J-major): out[g*32+co, v] = b[co] + sum_c W[co,c]X + W[co,32+c]Y + W[co,64+c]Z
// =======================================================================
__global__ __launch_bounds__(128)
void mixJ_kernel(const float* __restrict__ X, const float* __restrict__ Y,
                 const float* __restrict__ Z, const float* __restrict__ W,
                 const float* __restrict__ bias, float* __restrict__ out, int Vn)
{
    __shared__ float sW[96 * 32];
    __shared__ float sB[32];
    const int g = blockIdx.y;
    const int v = blockIdx.x * 128 + threadIdx.x;
    for (int i = threadIdx.x; i < 96 * 32; i += 128) {
        int co = i & 31, k = i >> 5;
        sW[i] = W[co * 96 + k];
    }
    if (threadIdx.x < 32) sB[threadIdx.x] = bias[threadIdx.x];
    __syncthreads();
    if (v >= Vn) return;

    float xv[32], yv[32], zv[32];
    const size_t base = (size_t)(g * 32) * Vn + v;
#pragma unroll
    for (int c = 0; c < 32; c++) {
        xv[c] = X[base + (size_t)c * Vn];
        yv[c] = Y[base + (size_t)c * Vn];
        zv[c] = Z[base + (size_t)c * Vn];
    }
#pragma unroll
    for (int co = 0; co < 32; co++) {
        float acc = sB[co];
#pragma unroll
        for (int c = 0; c < 32; c++) {
            acc += sW[c * 32 + co] * xv[c];
            acc += sW[(32 + c) * 32 + co] * yv[c];
            acc += sW[(64 + c) * 32 + co] * zv[c];
        }
        out[base + (size_t)co * Vn] = acc;
    }
}

// =======================================================================
// as_mat (mismatched flatten orders), sxj is [J, S]
// =======================================================================
__global__ __launch_bounds__(64)
void asmatJ_kernel() {
    const int s1 = blockIdx.x;
    const float* sxj = g_f + F_SX;
    __shared__ float a1[JD];
    for (int i = threadIdx.x; i < JD; i += 64) {
        int c = i / (NB * LL);
        int r = i - c * (NB * LL);
        int n = r / LL;
        int l = r - n * LL;
        a1[i] = sxj[(size_t)((n * LL + l) * CH + c) * SSZ + s1];
    }
    __syncthreads();
    const int s2 = threadIdx.x;
    float acc = 0.f;
    int i = 0;
    for (int l = 0; l < LL; l++)
        for (int n = 0; n < NB; n++) {
            const int j2 = (n * LL + l) * CH;
#pragma unroll
            for (int c = 0; c < CH; c++)
                acc += a1[i++] * sxj[(size_t)(j2 + c) * SSZ + s2];
        }
    g_as[s1 * SSZ + s2] = fmaxf(acc - 0.5f, 0.f);
}

// =======================================================================
// sup0 = softmax(rownorm(as)), sup1 = softmax(rownorm(as^T))
// =======================================================================
__global__ void supnorm_kernel() {
    __shared__ float sh[SSZ];
    const int s = blockIdx.x;
    const int t = threadIdx.x;
    float rv = g_as[s * SSZ + t];
    float cv = g_as[t * SSZ + s];

    sh[t] = rv; __syncthreads();
    for (int o = 32; o > 0; o >>= 1) { if (t < o) sh[t] += sh[t + o]; __syncthreads(); }
    float rs = sh[0]; __syncthreads();
    float xr = (rs > 0.f) ? rv / rs : 0.f;
    sh[t] = xr; __syncthreads();
    for (int o = 32; o > 0; o >>= 1) { if (t < o) sh[t] = fmaxf(sh[t], sh[t + o]); __syncthreads(); }
    float mx = sh[0]; __syncthreads();
    float e = expf(xr - mx);
    sh[t] = e; __syncthreads();
    for (int o = 32; o > 0; o >>= 1) { if (t < o) sh[t] += sh[t + o]; __syncthreads(); }
    g_sup0[s * SSZ + t] = e / sh[0];
    __syncthreads();

    sh[t] = cv; __syncthreads();
    for (int o = 32; o > 0; o >>= 1) { if (t < o) sh[t] += sh[t + o]; __syncthreads(); }
    float cs = sh[0]; __syncthreads();
    float xc2 = (cs > 0.f) ? cv / cs : 0.f;
    sh[t] = xc2; __syncthreads();
    for (int o = 32; o > 0; o >>= 1) { if (t < o) sh[t] = fmaxf(sh[t], sh[t + o]); __syncthreads(); }
    float mx2 = sh[0]; __syncthreads();
    float e2 = expf(xc2 - mx2);
    sh[t] = e2; __syncthreads();
    for (int o = 32; o > 0; o >>= 1) { if (t < o) sh[t] += sh[t + o]; __syncthreads(); }
    g_sup1[s * SSZ + t] = e2 / sh[0];
}

// =======================================================================
// pack J-major [J, R] back to [N, CO, R, L]
// =======================================================================
__global__ void pack_kernel(const float* __restrict__ src, int R, float* __restrict__ out) {
    size_t total = (size_t)NB * CH * R * LL;
    size_t idx = (size_t)blockIdx.x * blockDim.x + threadIdx.x;
    if (idx >= total) return;
    int l = (int)(idx % LL);
    size_t r1 = idx / LL;
    int v = (int)(r1 % R);
    size_t r2 = r1 / R;
    int co = (int)(r2 % CH);
    int n = (int)(r2 / CH);
    out[idx] = src[(size_t)((n * LL + l) * CH + co) * R + v];
}

// =======================================================================
extern "C" void kernel_launch(void* const* d_in, const int* in_sizes, int n_in,
                              void* d_out, int out_size)
{
    const float* x         = (const float*)d_in[0];
    const float* support   = (const float*)d_in[1];   // [2, V, V]
    const float* support_c = (const float*)d_in[2];   // [2, VC, VC]
    const float* acs       = (const float*)d_in[3];   // [VC, S]
    const float* afc       = (const float*)d_in[4];   // [V, VC]
    const float* W         = (const float*)d_in[5];   // [CO, 3C]
    const float* bias      = (const float*)d_in[6];   // [CO]
    float* out = (float*)d_out;

    float* gf;  cudaGetSymbolAddress((void**)&gf, g_f);
    bf16*  gb;  cudaGetSymbolAddress((void**)&gb, g_b);
    float* as0; cudaGetSymbolAddress((void**)&as0, g_sup0);
    float* as1; cudaGetSymbolAddress((void**)&as1, g_sup1);

    // smem: BN=128 stage=32KB x2 = 64KB ; BN=64 stage=24KB x2 = 48KB
    const int SM128 = 2 * (2 * 8192 + 2 * 128 * 32 * 2);
    const int SM64  = 2 * (2 * 8192 + 2 * 64 * 32 * 2);
    cudaFuncSetAttribute(gemm_mma<128, 0>, cudaFuncAttributeMaxDynamicSharedMemorySize, SM128);
    cudaFuncSetAttribute(gemm_mma<128, 1>, cudaFuncAttributeMaxDynamicSharedMemorySize, SM128);
    cudaFuncSetAttribute(gemm_mma<64, 0>,  cudaFuncAttributeMaxDynamicSharedMemorySize, SM64);
    cudaFuncSetAttribute(gemm_mma<64, 1>,  cudaFuncAttributeMaxDynamicSharedMemorySize, SM64);

    dim3 tb(32, 8);

    // ---- 1. input layout + weight conversions ----
    build_xj_kernel<<<(unsigned)((SZ_BIG + 255) / 256), 256>>>(x);
    tsplit_kernel<<<dim3(VV/32, VV/32), tb>>>(support,                 gb+B_ST1H, gb+B_ST1L, VV, VV);
    tsplit_kernel<<<dim3(VV/32, VV/32), tb>>>(support + (size_t)VV*VV, gb+B_ST2H, gb+B_ST2L, VV, VV);
    tsplit_kernel<<<dim3(VV/32, VCC/32), tb>>>(afc, gb+B_AFTH, gb+B_AFTL, VV, VCC);   // afcT [VC,V]
    split_kernel<<<(unsigned)(((size_t)VV*VCC + 255)/256), 256>>>(afc, gb+B_AFNH, gb+B_AFNL, (size_t)VV*VCC);
    tsplit_kernel<<<dim3(VCC/32, VCC/32), tb>>>(support_c,           gb+B_SC1H, gb+B_SC1L, VCC, VCC);
    tsplit_kernel<<<dim3(VCC/32, VCC/32), tb>>>(support_c + VCC*VCC, gb+B_SC2H, gb+B_SC2L, VCC, VCC);
    tsplit_kernel<<<dim3(VCC/32, SSZ/32), tb>>>(acs, gb+B_ACTH, gb+B_ACTL, VCC, SSZ); // acsT [S,VC]
    split_kernel<<<(unsigned)(((size_t)VCC*SSZ + 255)/256), 256>>>(acs, gb+B_ACNH, gb+B_ACNL, (size_t)VCC*SSZ);

    // ---- 2. fine nconv: t1 = xj . supT1^T, t2 ----
    {
        dim3 g(VV / 128, JD / 128);
        gemm_mma<128, 0><<<g, 256, SM128>>>(gb+B_XJH, gb+B_XJL, gb+B_ST1H, gb+B_ST1L, gf+F_T1, VV, VV, 0.f);
        gemm_mma<128, 0><<<g, 256, SM128>>>(gb+B_XJH, gb+B_XJL, gb+B_ST2H, gb+B_ST2L, gf+F_T2, VV, VV, 0.f);
    }
    // ---- 3. coarse projection: xc = xj . afcT^T ----
    {
        dim3 g(VCC / 128, JD / 128);
        gemm_mma<128, 0><<<g, 256, SM128>>>(gb+B_XJH, gb+B_XJL, gb+B_AFTH, gb+B_AFTL, gf+F_XC, VV, VCC, 0.f);
    }
    split_kernel<<<(unsigned)((SZ_MED + 255)/256), 256>>>(gf+F_XC, gb+B_XCH, gb+B_XCL, SZ_MED);

    // ---- 4. hf = gcn fine ----
    mixJ_kernel<<<dim3(VV/128, NB*LL), 128>>>(gf+F_XJ, gf+F_T1, gf+F_T2, W, bias, gf+F_HF, VV);

    // ---- 5. coarse nconv + gcn ----
    {
        dim3 g(VCC / 128, JD / 128);
        gemm_mma<128, 0><<<g, 256, SM128>>>(gb+B_XCH, gb+B_XCL, gb+B_SC1H, gb+B_SC1L, gf+F_C1, VCC, VCC, 0.f);
        gemm_mma<128, 0><<<g, 256, SM128>>>(gb+B_XCH, gb+B_XCL, gb+B_SC2H, gb+B_SC2L, gf+F_C2, VCC, VCC, 0.f);
    }
    mixJ_kernel<<<dim3(VCC/128, NB*LL), 128>>>(gf+F_XC, gf+F_C1, gf+F_C2, W, bias, gf+F_HC, VCC);

    // ---- 6. super projection: sx = xc . acsT^T ----
    {
        dim3 g(1, JD / 128);
        gemm_mma<64, 0><<<g, 256, SM64>>>(gb+B_XCH, gb+B_XCL, gb+B_ACTH, gb+B_ACTL, gf+F_SX, VCC, SSZ, 0.f);
    }
    split_kernel<<<(unsigned)((SZ_SML + 255)/256), 256>>>(gf+F_SX, gb+B_SXH, gb+B_SXL, SZ_SML);

    // ---- 7. adaptive supports ----
    asmatJ_kernel<<<SSZ, 64>>>();
    supnorm_kernel<<<SSZ, SSZ>>>();
    tsplit_kernel<<<dim3(SSZ/32, SSZ/32), tb>>>(as0, gb+B_SP0H, gb+B_SP0L, SSZ, SSZ);
    tsplit_kernel<<<dim3(SSZ/32, SSZ/32), tb>>>(as1, gb+B_SP1H, gb+B_SP1L, SSZ, SSZ);

    // ---- 8. super nconv + gcn ----
    {
        dim3 g(1, JD / 128);
        gemm_mma<64, 0><<<g, 256, SM64>>>(gb+B_SXH, gb+B_SXL, gb+B_SP0H, gb+B_SP0L, gf+F_S1, SSZ, SSZ, 0.f);
        gemm_mma<64, 0><<<g, 256, SM64>>>(gb+B_SXH, gb+B_SXL, gb+B_SP1H, gb+B_SP1L, gf+F_S2, SSZ, SSZ, 0.f);
    }
    mixJ_kernel<<<dim3(1, NB*LL), 128>>>(gf+F_SX, gf+F_S1, gf+F_S2, W, bias, gf+F_HS, SSZ);
    split_kernel<<<(unsigned)((SZ_SML + 255)/256), 256>>>(gf+F_HS, gb+B_HSH, gb+B_HSL, SZ_SML);

    // ---- 9. hierarchical residual fusions ----
    // hc += N1*relu(hs . acs^T)      [N=256, K=64]
    {
        dim3 g(VCC / 128, JD / 128);
        gemm_mma<128, 1><<<g, 256, SM128>>>(gb+B_HSH, gb+B_HSL, gb+B_ACNH, gb+B_ACNL, gf+F_HC, SSZ, VCC, FN1);
    }
    split_kernel<<<(unsigned)((SZ_MED + 255)/256), 256>>>(gf+F_HC, gb+B_HCH, gb+B_HCL, SZ_MED);
    // hf += N2*relu(hc . afc^T)      [N=2048, K=256]
    {
        dim3 g(VV / 128, JD / 128);
        gemm_mma<128, 1><<<g, 256, SM128>>>(gb+B_HCH, gb+B_HCL, gb+B_AFNH, gb+B_AFNL, gf+F_HF, VCC, VV, FN2);
    }
    split_kernel<<<(unsigned)((SZ_BIG + 255)/256), 256>>>(gf+F_HF, gb+B_HFH, gb+B_HFL, SZ_BIG);
    // hc += N3*relu(hf . afcT^T)     [N=256, K=2048]
    {
        dim3 g(VCC / 128, JD / 128);
        gemm_mma<128, 1><<<g, 256, SM128>>>(gb+B_HFH, gb+B_HFL, gb+B_AFTH, gb+B_AFTL, gf+F_HC, VV, VCC, FN3);
    }
    split_kernel<<<(unsigned)((SZ_MED + 255)/256), 256>>>(gf+F_HC, gb+B_HCH, gb+B_HCL, SZ_MED);
    // hs += N4*relu(hc . acsT^T)     [N=64, K=256]
    {
        dim3 g(1, JD / 128);
        gemm_mma<64, 1><<<g, 256, SM64>>>(gb+B_HCH, gb+B_HCL, gb+B_ACTH, gb+B_ACTL, gf+F_HS, VCC, SSZ, FN4);
    }

    // ---- 10. pack outputs ----
    const size_t off_hc = (size_t)NB * CH * VV * LL;
    const size_t off_hs = off_hc + (size_t)NB * CH * VCC * LL;
    {
        size_t tot = (size_t)NB * CH * VV * LL;
        pack_kernel<<<(unsigned)((tot + 255) / 256), 256>>>(gf+F_HF, VV, out);
    }
    {
        size_t tot = (size_t)NB * CH * VCC * LL;
        pack_kernel<<<(unsigned)((tot + 255) / 256), 256>>>(gf+F_HC, VCC, out + off_hc);
    }
    {
        size_t tot = (size_t)NB * CH * SSZ * LL;
        pack_kernel<<<(unsigned)((tot + 255) / 256), 256>>>(gf+F_HS, SSZ, out + off_hs);
    }
}